// round 6
// baseline (speedup 1.0000x reference)
#include <cuda_runtime.h>
#include <cstdint>
#include <math.h>

// ============================================================================
// get_model_pred — tf32 mma.sync, pre-rounded operands (no in-loop cvt).
//   edge_embed = relu(pred@We1+b1)@We2+b2
//   head       = softmax(relu(edge@Wt1+bt1)@Wt2+bt2) ; stack ; gate
// Outputs: types_w(4,E) | multiW(4,E) | type_output(E,4) | edge_embed(E,512)
// ============================================================================

#define D 512
#define E_MAX 89700

// Scratch (__device__ globals: cudaMalloc is forbidden)
__device__ float g_Ar [(size_t)E_MAX * D];   // tf32-rounded pred
__device__ float g_h  [(size_t)E_MAX * D];   // tf32-rounded hidden
__device__ float g_W1r[D * D];
__device__ float g_W2r[D * D];
__device__ float g_Wt1r[D * 128];

// SMEM tile layout (floats):
//   As [128][36]  (pad 4  -> conflict-free fragment loads)
//   Bs [32][136]  (pad 8)
#define AS_STRIDE 36
#define BS_STRIDE 136
#define AS_BYTES (128 * AS_STRIDE * 4)          // 18432
#define BS_BYTES (32 * BS_STRIDE * 4)           // 17408
#define STAGE_BYTES (AS_BYTES + BS_BYTES)       // 35840
#define NSTAGES 3
#define SMEM_TOTAL (NSTAGES * STAGE_BYTES)      // 107520

__device__ __forceinline__ uint32_t smem_u32(const void* p) {
    uint32_t a;
    asm("{ .reg .u64 t; cvta.to.shared.u64 t, %1; cvt.u32.u64 %0, t; }"
        : "=r"(a) : "l"(p));
    return a;
}
__device__ __forceinline__ uint32_t f2tf(float x) {   // round-to-nearest tf32
    uint32_t u;
    asm("cvt.rna.tf32.f32 %0, %1;" : "=r"(u) : "f"(x));
    return u;
}
__device__ __forceinline__ float rna_tf32f(float x) { return __uint_as_float(f2tf(x)); }
__device__ __forceinline__ float gatef(float p) {
    const float BEL = 0.025f;
    const float HI  = 1.0f / 2.2f + 0.025f;
    return (p <= BEL) ? 0.0f : ((p >= HI) ? 1.0f : 2.2f * (p - BEL));
}
__device__ __forceinline__ void cpa16(uint32_t dst, const void* src, bool valid) {
    int sz = valid ? 16 : 0;   // src-size 0 => zero-fill 16B
    asm volatile("cp.async.cg.shared.global [%0], [%1], 16, %2;"
                 :: "r"(dst), "l"(src), "r"(sz) : "memory");
}
#define CP_COMMIT() asm volatile("cp.async.commit_group;" ::: "memory")
#define CP_WAIT(n)  asm volatile("cp.async.wait_group %0;" :: "n"(n) : "memory")

__device__ __forceinline__ void mma_tf32(float& d0, float& d1, float& d2, float& d3,
                                         uint32_t a0, uint32_t a1, uint32_t a2, uint32_t a3,
                                         uint32_t b0, uint32_t b1) {
    asm volatile(
        "mma.sync.aligned.m16n8k8.row.col.f32.tf32.tf32.f32 "
        "{%0,%1,%2,%3}, {%4,%5,%6,%7}, {%8,%9}, {%0,%1,%2,%3};"
        : "+f"(d0), "+f"(d1), "+f"(d2), "+f"(d3)
        : "r"(a0), "r"(a1), "r"(a2), "r"(a3), "r"(b0), "r"(b1));
}

// ---------------------------------------------------------------------------
// Prep kernels: tf32-round inputs once (removes all cvt from GEMM mainloops)
// ---------------------------------------------------------------------------
__global__ void round_pred(const float4* __restrict__ in, float4* __restrict__ out, int n4) {
    int i = blockIdx.x * blockDim.x + threadIdx.x;
    if (i < n4) {
        float4 v = in[i];
        out[i] = make_float4(rna_tf32f(v.x), rna_tf32f(v.y), rna_tf32f(v.z), rna_tf32f(v.w));
    }
}
// W1,W2: 65536 float4 each; Wt1: 16384 float4. Total 147456 slots.
__global__ void round_weights(const float4* __restrict__ W1, const float4* __restrict__ W2,
                              const float4* __restrict__ Wt1, float4* __restrict__ o1,
                              float4* __restrict__ o2, float4* __restrict__ o3) {
    int i = blockIdx.x * blockDim.x + threadIdx.x;
    const float4* src; float4* dst; int j;
    if (i < 65536)        { src = W1;  dst = o1; j = i; }
    else if (i < 131072)  { src = W2;  dst = o2; j = i - 65536; }
    else if (i < 147456)  { src = Wt1; dst = o3; j = i - 131072; }
    else return;
    float4 v = src[j];
    dst[j] = make_float4(rna_tf32f(v.x), rna_tf32f(v.y), rna_tf32f(v.z), rna_tf32f(v.w));
}

// ---------------------------------------------------------------------------
// Stage loader. A: (E x D) row-major; B: (D x NW) row-major.
// ---------------------------------------------------------------------------
template <int NW>
__device__ __forceinline__ void load_tile(
    uint32_t sA, uint32_t sB, const float* __restrict__ Ag,
    const float* __restrict__ Bg, int rowBase, int colBase, int kb, int E, int tid)
{
#pragma unroll
    for (int i = 0; i < 4; i++) {                   // A: 1024 float4 slots
        int idx = i * 256 + tid;
        int row = idx >> 3, f4 = (idx & 7) << 2;
        bool v = (rowBase + row) < E;
        const float* src = Ag + (size_t)(rowBase + row) * D + kb + f4;
        cpa16(sA + (uint32_t)(row * AS_STRIDE + f4) * 4, v ? src : Ag, v);
    }
#pragma unroll
    for (int i = 0; i < 4; i++) {                   // B: 32 rows x 32 float4
        int idx = i * 256 + tid;
        int k = idx >> 5, f4 = (idx & 31) << 2;
        const float* src = Bg + (size_t)(kb + k) * NW + colBase + f4;
        cpa16(sB + (uint32_t)(k * BS_STRIDE + f4) * 4, src, true);
    }
}

// Warp-tile compute on one 32-deep K chunk. CVTA: round A fragments in-loop
// (only the head kernel needs it; everything else reads pre-rounded data).
template <bool CVTA>
__device__ __forceinline__ void compute_tile(
    const float* As, const float* Bs, float acc[4][4][4],
    int wm, int wn, int gid, int tig)
{
    const uint32_t* Au = (const uint32_t*)As;
    const uint32_t* Bu = (const uint32_t*)Bs;
#pragma unroll
    for (int ks = 0; ks < 4; ks++) {
        const int k = ks * 8 + tig;
        uint32_t a[4][4], b[4][2];
#pragma unroll
        for (int mt = 0; mt < 4; mt++) {
            const int m = wm * 64 + mt * 16 + gid;
            if (CVTA) {
                a[mt][0] = f2tf(As[m * AS_STRIDE + k]);
                a[mt][1] = f2tf(As[(m + 8) * AS_STRIDE + k]);
                a[mt][2] = f2tf(As[m * AS_STRIDE + k + 4]);
                a[mt][3] = f2tf(As[(m + 8) * AS_STRIDE + k + 4]);
            } else {
                a[mt][0] = Au[m * AS_STRIDE + k];
                a[mt][1] = Au[(m + 8) * AS_STRIDE + k];
                a[mt][2] = Au[m * AS_STRIDE + k + 4];
                a[mt][3] = Au[(m + 8) * AS_STRIDE + k + 4];
            }
        }
#pragma unroll
        for (int nt = 0; nt < 4; nt++) {
            const int n = wn * 32 + nt * 8 + gid;
            b[nt][0] = Bu[k * BS_STRIDE + n];
            b[nt][1] = Bu[(k + 4) * BS_STRIDE + n];
        }
#pragma unroll
        for (int mt = 0; mt < 4; mt++)
#pragma unroll
            for (int nt = 0; nt < 4; nt++)
                mma_tf32(acc[mt][nt][0], acc[mt][nt][1], acc[mt][nt][2], acc[mt][nt][3],
                         a[mt][0], a[mt][1], a[mt][2], a[mt][3],
                         b[nt][0], b[nt][1]);
    }
}

template <int NW, bool CVTA>
__device__ __forceinline__ void gemm_mainloop(
    char* smem, const float* __restrict__ Ag, const float* __restrict__ Bg,
    int rowBase, int colBase, int E, int tid, float acc[4][4][4],
    int wm, int wn, int gid, int tig)
{
    const uint32_t sb = smem_u32(smem);

#pragma unroll
    for (int mt = 0; mt < 4; mt++)
#pragma unroll
        for (int nt = 0; nt < 4; nt++)
#pragma unroll
            for (int r = 0; r < 4; r++) acc[mt][nt][r] = 0.0f;

    load_tile<NW>(sb, sb + AS_BYTES, Ag, Bg, rowBase, colBase, 0, E, tid);
    CP_COMMIT();
    load_tile<NW>(sb + STAGE_BYTES, sb + STAGE_BYTES + AS_BYTES,
                  Ag, Bg, rowBase, colBase, 32, E, tid);
    CP_COMMIT();

    for (int kt = 0; kt < 16; kt++) {
        CP_WAIT(1);
        __syncthreads();
        if (kt + 2 < 16) {
            uint32_t st = sb + (uint32_t)((kt + 2) % NSTAGES) * STAGE_BYTES;
            load_tile<NW>(st, st + AS_BYTES, Ag, Bg, rowBase, colBase,
                          (kt + 2) * 32, E, tid);
        }
        CP_COMMIT();
        const float* As = (const float*)(smem + (kt % NSTAGES) * STAGE_BYTES);
        const float* Bs = As + 128 * AS_STRIDE;
        compute_tile<CVTA>(As, Bs, acc, wm, wn, gid, tig);
    }
    CP_WAIT(0);
    __syncthreads();
}

// ---------------------------------------------------------------------------
// Big GEMM: C(E x 512) = A @ B(512x512) + bias. Grid (rb, 4).
// RELU_ROUND: gemm1 writes rna(relu(v)) so gemm2 needs no in-loop cvt.
// ---------------------------------------------------------------------------
template <bool RELU_ROUND>
__global__ __launch_bounds__(256, 2) void gemm_mma(
    const float* __restrict__ Ag, const float* __restrict__ Bg,
    const float* __restrict__ bias, float* __restrict__ C, int E)
{
    extern __shared__ __align__(16) char smem[];
    __shared__ float sbias[128];

    const int tid = threadIdx.x;
    const int wid = tid >> 5, lane = tid & 31;
    const int wm = wid >> 2, wn = wid & 3;       // 2 x 4 warp grid
    const int gid = lane >> 2, tig = lane & 3;
    const int rowBase = blockIdx.x * 128;
    const int colBase = blockIdx.y * 128;

    if (tid < 128) sbias[tid] = bias[colBase + tid];

    float acc[4][4][4];
    gemm_mainloop<D, false>(smem, Ag, Bg, rowBase, colBase, E, tid, acc, wm, wn, gid, tig);

#pragma unroll
    for (int mt = 0; mt < 4; mt++) {
        const int r0 = rowBase + wm * 64 + mt * 16 + gid;
#pragma unroll
        for (int nt = 0; nt < 4; nt++) {
            const int cl = wn * 32 + nt * 8 + tig * 2;
            const int c = colBase + cl;
            float v0 = acc[mt][nt][0] + sbias[cl];
            float v1 = acc[mt][nt][1] + sbias[cl + 1];
            float v2 = acc[mt][nt][2] + sbias[cl];
            float v3 = acc[mt][nt][3] + sbias[cl + 1];
            if (RELU_ROUND) {
                v0 = rna_tf32f(fmaxf(v0, 0.f)); v1 = rna_tf32f(fmaxf(v1, 0.f));
                v2 = rna_tf32f(fmaxf(v2, 0.f)); v3 = rna_tf32f(fmaxf(v3, 0.f));
            }
            if (r0 < E)     *(float2*)&C[(size_t)r0 * D + c]       = make_float2(v0, v1);
            if (r0 + 8 < E) *(float2*)&C[(size_t)(r0 + 8) * D + c] = make_float2(v2, v3);
        }
    }
}

// ---------------------------------------------------------------------------
// Head: T1 = relu(edge @ Wt1 + bt1) (128x128, K=512), then per-row 128->4
// GEMV + softmax + stack + gate + small outputs. Grid (rb).
// A = exact edge (in-loop cvt); B = pre-rounded Wt1.
// ---------------------------------------------------------------------------
__global__ __launch_bounds__(256, 2) void head_mma(
    const float* __restrict__ EE, const float* __restrict__ Wt1,
    const float* __restrict__ bt1, const float* __restrict__ Wt2,
    const float* __restrict__ bt2, float* __restrict__ out, int E)
{
    extern __shared__ __align__(16) char smem[];
    __shared__ float sWt2[512];
    __shared__ float sbt1[128];

    const int tid = threadIdx.x;
    const int wid = tid >> 5, lane = tid & 31;
    const int wm = wid >> 2, wn = wid & 3;
    const int gid = lane >> 2, tig = lane & 3;
    const int rowBase = blockIdx.x * 128;

    if (tid < 128) {
        sbt1[tid] = bt1[tid];
        sWt2[tid]       = Wt2[tid];
        sWt2[tid + 128] = Wt2[tid + 128];
        sWt2[tid + 256] = Wt2[tid + 256];
        sWt2[tid + 384] = Wt2[tid + 384];
    }

    float acc[4][4][4];
    gemm_mainloop<128, true>(smem, EE, Wt1, rowBase, 0, E, tid, acc, wm, wn, gid, tig);

    // T1 -> padded slab [128][129] (reuses pipeline smem after CP_WAIT(0)+sync)
    float* T1 = (float*)smem;
#pragma unroll
    for (int mt = 0; mt < 4; mt++) {
        const int r = wm * 64 + mt * 16 + gid;
#pragma unroll
        for (int nt = 0; nt < 4; nt++) {
            const int c = wn * 32 + nt * 8 + tig * 2;
            T1[r * 129 + c]           = fmaxf(acc[mt][nt][0] + sbt1[c], 0.f);
            T1[r * 129 + c + 1]       = fmaxf(acc[mt][nt][1] + sbt1[c + 1], 0.f);
            T1[(r + 8) * 129 + c]     = fmaxf(acc[mt][nt][2] + sbt1[c], 0.f);
            T1[(r + 8) * 129 + c + 1] = fmaxf(acc[mt][nt][3] + sbt1[c + 1], 0.f);
        }
    }
    __syncthreads();

    if (tid < 128) {
        const int gr = rowBase + tid;
        if (gr < E) {
            float t0 = __ldg(&bt2[0]), t1 = __ldg(&bt2[1]);
            float t2 = __ldg(&bt2[2]), t3 = __ldg(&bt2[3]);
            const float* rp = T1 + tid * 129;
#pragma unroll 8
            for (int k = 0; k < 128; k++) {
                float x = rp[k];
                t0 = fmaf(x, sWt2[k * 4 + 0], t0);
                t1 = fmaf(x, sWt2[k * 4 + 1], t1);
                t2 = fmaf(x, sWt2[k * 4 + 2], t2);
                t3 = fmaf(x, sWt2[k * 4 + 3], t3);
            }
            float m = fmaxf(fmaxf(t0, t1), fmaxf(t2, t3));
            float e0 = __expf(t0 - m), e1 = __expf(t1 - m);
            float e2 = __expf(t2 - m), e3 = __expf(t3 - m);
            float inv = 1.0f / (e0 + e1 + e2 + e3);
            float p0 = e0 * inv, p1 = e1 * inv, p2 = e2 * inv, p3 = e3 * inv;
            float tw0 = 1.0f - p0;

            const size_t Es = (size_t)E;
            out[0 * Es + gr] = tw0;
            out[1 * Es + gr] = p1;
            out[2 * Es + gr] = p2;
            out[3 * Es + gr] = p3;
            float* mw = out + 4 * Es;
            mw[0 * Es + gr] = gatef(tw0);
            mw[1 * Es + gr] = gatef(p1);
            mw[2 * Es + gr] = gatef(p2);
            mw[3 * Es + gr] = gatef(p3);
            float* to = out + 8 * Es;
            to[(size_t)gr * 4 + 0] = p0;
            to[(size_t)gr * 4 + 1] = p1;
            to[(size_t)gr * 4 + 2] = p2;
            to[(size_t)gr * 4 + 3] = p3;
        }
    }
}

// ---------------------------------------------------------------------------
extern "C" void kernel_launch(void* const* d_in, const int* in_sizes, int n_in,
                              void* d_out, int out_size)
{
    const float* pred = (const float*)d_in[1];
    const float* We1  = (const float*)d_in[2];
    const float* be1  = (const float*)d_in[3];
    const float* We2  = (const float*)d_in[4];
    const float* be2  = (const float*)d_in[5];
    const float* Wt1  = (const float*)d_in[6];
    const float* bt1  = (const float*)d_in[7];
    const float* Wt2  = (const float*)d_in[8];
    const float* bt2  = (const float*)d_in[9];

    const int E = in_sizes[1] / D;
    float* out  = (float*)d_out;
    float* edge = out + (size_t)12 * E;

    float *pAr, *pH, *pW1r, *pW2r, *pWt1r;
    cudaGetSymbolAddress((void**)&pAr,  g_Ar);
    cudaGetSymbolAddress((void**)&pH,   g_h);
    cudaGetSymbolAddress((void**)&pW1r, g_W1r);
    cudaGetSymbolAddress((void**)&pW2r, g_W2r);
    cudaGetSymbolAddress((void**)&pWt1r, g_Wt1r);

    cudaFuncSetAttribute(gemm_mma<true>,
                         cudaFuncAttributeMaxDynamicSharedMemorySize, SMEM_TOTAL);
    cudaFuncSetAttribute(gemm_mma<false>,
                         cudaFuncAttributeMaxDynamicSharedMemorySize, SMEM_TOTAL);
    cudaFuncSetAttribute(head_mma,
                         cudaFuncAttributeMaxDynamicSharedMemorySize, SMEM_TOTAL);

    // Prep: tf32-round pred + weights once.
    const int n4 = E * D / 4;
    round_pred<<<(n4 + 255) / 256, 256>>>((const float4*)pred, (float4*)pAr, n4);
    round_weights<<<(147456 + 255) / 256, 256>>>(
        (const float4*)We1, (const float4*)We2, (const float4*)Wt1,
        (float4*)pW1r, (float4*)pW2r, (float4*)pWt1r);

    const int rb = (E + 127) / 128;
    dim3 grid(rb, 4);

    gemm_mma<true ><<<grid, 256, SMEM_TOTAL>>>(pAr, pW1r, be1, pH, E);     // h = rna(relu(...))
    gemm_mma<false><<<grid, 256, SMEM_TOTAL>>>(pH,  pW2r, be2, edge, E);   // edge exact
    head_mma<<<rb, 256, SMEM_TOTAL>>>(edge, pWt1r, bt1, Wt2, bt2, out, E);
}

// round 7
// speedup vs baseline: 1.4112x; 1.4112x over previous
#include <cuda_runtime.h>
#include <cstdint>
#include <math.h>

// ============================================================================
// get_model_pred — tf32 mma.sync, pre-rounded operands, 512-thr/CTA for
// 8 warps/SMSP (latency-bound fix for R6's 4-warp/SMSP stall).
//   edge_embed = relu(pred@We1+b1)@We2+b2
//   head       = softmax(relu(edge@Wt1+bt1)@Wt2+bt2) ; stack ; gate
// Outputs: types_w(4,E) | multiW(4,E) | type_output(E,4) | edge_embed(E,512)
// ============================================================================

#define D 512
#define E_MAX 89700

// Scratch (__device__ globals: cudaMalloc is forbidden)
__device__ float g_Ar [(size_t)E_MAX * D];   // tf32-rounded pred
__device__ float g_h  [(size_t)E_MAX * D];   // tf32-rounded hidden
__device__ float g_W1r[D * D];
__device__ float g_W2r[D * D];
__device__ float g_Wt1r[D * 128];

// SMEM tiles: As [128][36] (pad 4), Bs [32][136] (pad 8) — conflict-free
#define AS_STRIDE 36
#define BS_STRIDE 136
#define AS_BYTES (128 * AS_STRIDE * 4)          // 18432
#define BS_BYTES (32 * BS_STRIDE * 4)           // 17408
#define STAGE_BYTES (AS_BYTES + BS_BYTES)       // 35840
#define NSTAGES 3
#define SMEM_TOTAL (NSTAGES * STAGE_BYTES)      // 107520
#define NTHREADS 512

__device__ __forceinline__ uint32_t smem_u32(const void* p) {
    uint32_t a;
    asm("{ .reg .u64 t; cvta.to.shared.u64 t, %1; cvt.u32.u64 %0, t; }"
        : "=r"(a) : "l"(p));
    return a;
}
__device__ __forceinline__ uint32_t f2tf(float x) {   // round-to-nearest tf32
    uint32_t u;
    asm("cvt.rna.tf32.f32 %0, %1;" : "=r"(u) : "f"(x));
    return u;
}
__device__ __forceinline__ float rna_tf32f(float x) { return __uint_as_float(f2tf(x)); }
__device__ __forceinline__ float gatef(float p) {
    const float BEL = 0.025f;
    const float HI  = 1.0f / 2.2f + 0.025f;
    return (p <= BEL) ? 0.0f : ((p >= HI) ? 1.0f : 2.2f * (p - BEL));
}
__device__ __forceinline__ void cpa16(uint32_t dst, const void* src, bool valid) {
    int sz = valid ? 16 : 0;   // src-size 0 => zero-fill 16B
    asm volatile("cp.async.cg.shared.global [%0], [%1], 16, %2;"
                 :: "r"(dst), "l"(src), "r"(sz) : "memory");
}
#define CP_COMMIT() asm volatile("cp.async.commit_group;" ::: "memory")
#define CP_WAIT(n)  asm volatile("cp.async.wait_group %0;" :: "n"(n) : "memory")

__device__ __forceinline__ void mma_tf32(float& d0, float& d1, float& d2, float& d3,
                                         uint32_t a0, uint32_t a1, uint32_t a2, uint32_t a3,
                                         uint32_t b0, uint32_t b1) {
    asm volatile(
        "mma.sync.aligned.m16n8k8.row.col.f32.tf32.tf32.f32 "
        "{%0,%1,%2,%3}, {%4,%5,%6,%7}, {%8,%9}, {%0,%1,%2,%3};"
        : "+f"(d0), "+f"(d1), "+f"(d2), "+f"(d3)
        : "r"(a0), "r"(a1), "r"(a2), "r"(a3), "r"(b0), "r"(b1));
}

// ---------------------------------------------------------------------------
// Prep kernels: tf32-round inputs once
// ---------------------------------------------------------------------------
__global__ void round_pred(const float4* __restrict__ in, float4* __restrict__ out, int n4) {
    int i = blockIdx.x * blockDim.x + threadIdx.x;
    if (i < n4) {
        float4 v = in[i];
        out[i] = make_float4(rna_tf32f(v.x), rna_tf32f(v.y), rna_tf32f(v.z), rna_tf32f(v.w));
    }
}
__global__ void round_weights(const float4* __restrict__ W1, const float4* __restrict__ W2,
                              const float4* __restrict__ Wt1, float4* __restrict__ o1,
                              float4* __restrict__ o2, float4* __restrict__ o3) {
    int i = blockIdx.x * blockDim.x + threadIdx.x;
    const float4* src; float4* dst; int j;
    if (i < 65536)        { src = W1;  dst = o1; j = i; }
    else if (i < 131072)  { src = W2;  dst = o2; j = i - 65536; }
    else if (i < 147456)  { src = Wt1; dst = o3; j = i - 131072; }
    else return;
    float4 v = src[j];
    dst[j] = make_float4(rna_tf32f(v.x), rna_tf32f(v.y), rna_tf32f(v.z), rna_tf32f(v.w));
}

// ---------------------------------------------------------------------------
// Stage loader (512 threads). A: (E x D) row-major; B: (D x NW) row-major.
// ---------------------------------------------------------------------------
template <int NW>
__device__ __forceinline__ void load_tile(
    uint32_t sA, uint32_t sB, const float* __restrict__ Ag,
    const float* __restrict__ Bg, int rowBase, int colBase, int kb, int E, int tid)
{
#pragma unroll
    for (int i = 0; i < 2; i++) {                   // A: 1024 float4 slots
        int idx = i * NTHREADS + tid;
        int row = idx >> 3, f4 = (idx & 7) << 2;
        bool v = (rowBase + row) < E;
        const float* src = Ag + (size_t)(rowBase + row) * D + kb + f4;
        cpa16(sA + (uint32_t)(row * AS_STRIDE + f4) * 4, v ? src : Ag, v);
    }
#pragma unroll
    for (int i = 0; i < 2; i++) {                   // B: 32 rows x 32 float4
        int idx = i * NTHREADS + tid;
        int k = idx >> 5, f4 = (idx & 31) << 2;
        const float* src = Bg + (size_t)(kb + k) * NW + colBase + f4;
        cpa16(sB + (uint32_t)(k * BS_STRIDE + f4) * 4, src, true);
    }
}

// Warp-tile (32x32) compute on one 32-deep K chunk. 4x4 warp grid.
// CVTA: round A fragments in-loop (head kernel only).
template <bool CVTA>
__device__ __forceinline__ void compute_tile(
    const float* As, const float* Bs, float acc[2][4][4],
    int wm, int wn, int gid, int tig)
{
    const uint32_t* Au = (const uint32_t*)As;
    const uint32_t* Bu = (const uint32_t*)Bs;
#pragma unroll
    for (int ks = 0; ks < 4; ks++) {
        const int k = ks * 8 + tig;
        uint32_t a[2][4], b[4][2];
#pragma unroll
        for (int mt = 0; mt < 2; mt++) {
            const int m = wm * 32 + mt * 16 + gid;
            if (CVTA) {
                a[mt][0] = f2tf(As[m * AS_STRIDE + k]);
                a[mt][1] = f2tf(As[(m + 8) * AS_STRIDE + k]);
                a[mt][2] = f2tf(As[m * AS_STRIDE + k + 4]);
                a[mt][3] = f2tf(As[(m + 8) * AS_STRIDE + k + 4]);
            } else {
                a[mt][0] = Au[m * AS_STRIDE + k];
                a[mt][1] = Au[(m + 8) * AS_STRIDE + k];
                a[mt][2] = Au[m * AS_STRIDE + k + 4];
                a[mt][3] = Au[(m + 8) * AS_STRIDE + k + 4];
            }
        }
#pragma unroll
        for (int nt = 0; nt < 4; nt++) {
            const int n = wn * 32 + nt * 8 + gid;
            b[nt][0] = Bu[k * BS_STRIDE + n];
            b[nt][1] = Bu[(k + 4) * BS_STRIDE + n];
        }
#pragma unroll
        for (int mt = 0; mt < 2; mt++)
#pragma unroll
            for (int nt = 0; nt < 4; nt++)
                mma_tf32(acc[mt][nt][0], acc[mt][nt][1], acc[mt][nt][2], acc[mt][nt][3],
                         a[mt][0], a[mt][1], a[mt][2], a[mt][3],
                         b[nt][0], b[nt][1]);
    }
}

template <int NW, bool CVTA>
__device__ __forceinline__ void gemm_mainloop(
    char* smem, const float* __restrict__ Ag, const float* __restrict__ Bg,
    int rowBase, int colBase, int E, int tid, float acc[2][4][4],
    int wm, int wn, int gid, int tig)
{
    const uint32_t sb = smem_u32(smem);

#pragma unroll
    for (int mt = 0; mt < 2; mt++)
#pragma unroll
        for (int nt = 0; nt < 4; nt++)
#pragma unroll
            for (int r = 0; r < 4; r++) acc[mt][nt][r] = 0.0f;

    load_tile<NW>(sb, sb + AS_BYTES, Ag, Bg, rowBase, colBase, 0, E, tid);
    CP_COMMIT();
    load_tile<NW>(sb + STAGE_BYTES, sb + STAGE_BYTES + AS_BYTES,
                  Ag, Bg, rowBase, colBase, 32, E, tid);
    CP_COMMIT();

    for (int kt = 0; kt < 16; kt++) {
        CP_WAIT(1);
        __syncthreads();
        if (kt + 2 < 16) {
            uint32_t st = sb + (uint32_t)((kt + 2) % NSTAGES) * STAGE_BYTES;
            load_tile<NW>(st, st + AS_BYTES, Ag, Bg, rowBase, colBase,
                          (kt + 2) * 32, E, tid);
        }
        CP_COMMIT();
        const float* As = (const float*)(smem + (kt % NSTAGES) * STAGE_BYTES);
        const float* Bs = As + 128 * AS_STRIDE;
        compute_tile<CVTA>(As, Bs, acc, wm, wn, gid, tig);
    }
    CP_WAIT(0);
    __syncthreads();
}

// ---------------------------------------------------------------------------
// Big GEMM: C(E x 512) = A @ B(512x512) + bias. Grid (rb, 4), 512 thr.
// RELU_ROUND: gemm1 writes rna(relu(v)) so gemm2 needs no in-loop cvt.
// ---------------------------------------------------------------------------
template <bool RELU_ROUND>
__global__ __launch_bounds__(NTHREADS, 2) void gemm_mma(
    const float* __restrict__ Ag, const float* __restrict__ Bg,
    const float* __restrict__ bias, float* __restrict__ C, int E)
{
    extern __shared__ __align__(16) char smem[];
    __shared__ float sbias[128];

    const int tid = threadIdx.x;
    const int wid = tid >> 5, lane = tid & 31;
    const int wm = wid >> 2, wn = wid & 3;       // 4 x 4 warp grid
    const int gid = lane >> 2, tig = lane & 3;
    const int rowBase = blockIdx.x * 128;
    const int colBase = blockIdx.y * 128;

    if (tid < 128) sbias[tid] = bias[colBase + tid];

    float acc[2][4][4];
    gemm_mainloop<D, false>(smem, Ag, Bg, rowBase, colBase, E, tid, acc, wm, wn, gid, tig);

#pragma unroll
    for (int mt = 0; mt < 2; mt++) {
        const int r0 = rowBase + wm * 32 + mt * 16 + gid;
#pragma unroll
        for (int nt = 0; nt < 4; nt++) {
            const int cl = wn * 32 + nt * 8 + tig * 2;
            const int c = colBase + cl;
            float v0 = acc[mt][nt][0] + sbias[cl];
            float v1 = acc[mt][nt][1] + sbias[cl + 1];
            float v2 = acc[mt][nt][2] + sbias[cl];
            float v3 = acc[mt][nt][3] + sbias[cl + 1];
            if (RELU_ROUND) {
                v0 = rna_tf32f(fmaxf(v0, 0.f)); v1 = rna_tf32f(fmaxf(v1, 0.f));
                v2 = rna_tf32f(fmaxf(v2, 0.f)); v3 = rna_tf32f(fmaxf(v3, 0.f));
            }
            if (r0 < E)     *(float2*)&C[(size_t)r0 * D + c]       = make_float2(v0, v1);
            if (r0 + 8 < E) *(float2*)&C[(size_t)(r0 + 8) * D + c] = make_float2(v2, v3);
        }
    }
}

// ---------------------------------------------------------------------------
// Head: T1 = relu(edge @ Wt1 + bt1) (128x128, K=512), then per-row 128->4
// GEMV + softmax + stack + gate + small outputs. Grid (rb), 512 thr.
// A = exact edge (in-loop cvt); B = pre-rounded Wt1.
// ---------------------------------------------------------------------------
__global__ __launch_bounds__(NTHREADS, 2) void head_mma(
    const float* __restrict__ EE, const float* __restrict__ Wt1,
    const float* __restrict__ bt1, const float* __restrict__ Wt2,
    const float* __restrict__ bt2, float* __restrict__ out, int E)
{
    extern __shared__ __align__(16) char smem[];
    __shared__ float sWt2[512];
    __shared__ float sbt1[128];

    const int tid = threadIdx.x;
    const int wid = tid >> 5, lane = tid & 31;
    const int wm = wid >> 2, wn = wid & 3;
    const int gid = lane >> 2, tig = lane & 3;
    const int rowBase = blockIdx.x * 128;

    if (tid < 128) {
        sbt1[tid] = bt1[tid];
        sWt2[tid]       = Wt2[tid];
        sWt2[tid + 128] = Wt2[tid + 128];
        sWt2[tid + 256] = Wt2[tid + 256];
        sWt2[tid + 384] = Wt2[tid + 384];
    }

    float acc[2][4][4];
    gemm_mainloop<128, true>(smem, EE, Wt1, rowBase, 0, E, tid, acc, wm, wn, gid, tig);

    // T1 -> padded slab [128][129] (reuses pipeline smem after CP_WAIT(0)+sync)
    float* T1 = (float*)smem;
#pragma unroll
    for (int mt = 0; mt < 2; mt++) {
        const int r = wm * 32 + mt * 16 + gid;
#pragma unroll
        for (int nt = 0; nt < 4; nt++) {
            const int c = wn * 32 + nt * 8 + tig * 2;
            T1[r * 129 + c]           = fmaxf(acc[mt][nt][0] + sbt1[c], 0.f);
            T1[r * 129 + c + 1]       = fmaxf(acc[mt][nt][1] + sbt1[c + 1], 0.f);
            T1[(r + 8) * 129 + c]     = fmaxf(acc[mt][nt][2] + sbt1[c], 0.f);
            T1[(r + 8) * 129 + c + 1] = fmaxf(acc[mt][nt][3] + sbt1[c + 1], 0.f);
        }
    }
    __syncthreads();

    if (tid < 128) {
        const int gr = rowBase + tid;
        if (gr < E) {
            float t0 = __ldg(&bt2[0]), t1 = __ldg(&bt2[1]);
            float t2 = __ldg(&bt2[2]), t3 = __ldg(&bt2[3]);
            const float* rp = T1 + tid * 129;
#pragma unroll 8
            for (int k = 0; k < 128; k++) {
                float x = rp[k];
                t0 = fmaf(x, sWt2[k * 4 + 0], t0);
                t1 = fmaf(x, sWt2[k * 4 + 1], t1);
                t2 = fmaf(x, sWt2[k * 4 + 2], t2);
                t3 = fmaf(x, sWt2[k * 4 + 3], t3);
            }
            float m = fmaxf(fmaxf(t0, t1), fmaxf(t2, t3));
            float e0 = __expf(t0 - m), e1 = __expf(t1 - m);
            float e2 = __expf(t2 - m), e3 = __expf(t3 - m);
            float inv = 1.0f / (e0 + e1 + e2 + e3);
            float p0 = e0 * inv, p1 = e1 * inv, p2 = e2 * inv, p3 = e3 * inv;
            float tw0 = 1.0f - p0;

            const size_t Es = (size_t)E;
            out[0 * Es + gr] = tw0;
            out[1 * Es + gr] = p1;
            out[2 * Es + gr] = p2;
            out[3 * Es + gr] = p3;
            float* mw = out + 4 * Es;
            mw[0 * Es + gr] = gatef(tw0);
            mw[1 * Es + gr] = gatef(p1);
            mw[2 * Es + gr] = gatef(p2);
            mw[3 * Es + gr] = gatef(p3);
            float* to = out + 8 * Es;
            to[(size_t)gr * 4 + 0] = p0;
            to[(size_t)gr * 4 + 1] = p1;
            to[(size_t)gr * 4 + 2] = p2;
            to[(size_t)gr * 4 + 3] = p3;
        }
    }
}

// ---------------------------------------------------------------------------
extern "C" void kernel_launch(void* const* d_in, const int* in_sizes, int n_in,
                              void* d_out, int out_size)
{
    const float* pred = (const float*)d_in[1];
    const float* We1  = (const float*)d_in[2];
    const float* be1  = (const float*)d_in[3];
    const float* We2  = (const float*)d_in[4];
    const float* be2  = (const float*)d_in[5];
    const float* Wt1  = (const float*)d_in[6];
    const float* bt1  = (const float*)d_in[7];
    const float* Wt2  = (const float*)d_in[8];
    const float* bt2  = (const float*)d_in[9];

    const int E = in_sizes[1] / D;
    float* out  = (float*)d_out;
    float* edge = out + (size_t)12 * E;

    float *pAr, *pH, *pW1r, *pW2r, *pWt1r;
    cudaGetSymbolAddress((void**)&pAr,  g_Ar);
    cudaGetSymbolAddress((void**)&pH,   g_h);
    cudaGetSymbolAddress((void**)&pW1r, g_W1r);
    cudaGetSymbolAddress((void**)&pW2r, g_W2r);
    cudaGetSymbolAddress((void**)&pWt1r, g_Wt1r);

    cudaFuncSetAttribute(gemm_mma<true>,
                         cudaFuncAttributeMaxDynamicSharedMemorySize, SMEM_TOTAL);
    cudaFuncSetAttribute(gemm_mma<false>,
                         cudaFuncAttributeMaxDynamicSharedMemorySize, SMEM_TOTAL);
    cudaFuncSetAttribute(head_mma,
                         cudaFuncAttributeMaxDynamicSharedMemorySize, SMEM_TOTAL);

    // Prep: tf32-round pred + weights once.
    const int n4 = E * D / 4;
    round_pred<<<(n4 + 255) / 256, 256>>>((const float4*)pred, (float4*)pAr, n4);
    round_weights<<<(147456 + 255) / 256, 256>>>(
        (const float4*)We1, (const float4*)We2, (const float4*)Wt1,
        (float4*)pW1r, (float4*)pW2r, (float4*)pWt1r);

    const int rb = (E + 127) / 128;
    dim3 grid(rb, 4);

    gemm_mma<true ><<<grid, NTHREADS, SMEM_TOTAL>>>(pAr, pW1r, be1, pH, E);   // h = rna(relu(...))
    gemm_mma<false><<<grid, NTHREADS, SMEM_TOTAL>>>(pH,  pW2r, be2, edge, E); // edge exact
    head_mma<<<rb, NTHREADS, SMEM_TOTAL>>>(edge, pWt1r, bt1, Wt2, bt2, out, E);
}